// round 14
// baseline (speedup 1.0000x reference)
#include <cuda_runtime.h>
#include <math.h>

// ---------------------------------------------------------------------------
// HSGNN forward, GB300.  Sparse-bitmask pipeline, 5 kernels.
// K1: pure linear adj stream -> mask words via ballot + Morton spread.
// ---------------------------------------------------------------------------

#define NN 5000
#define WPR 157      // ceil(5000/32) words per bitmask row
#define WPRP 160     // padded words per row (= 40 chunks x 4 words)
#define DOUT 16
#define NCLS 100

__device__ unsigned g_bits[3][NN * WPRP];   // per-meta-path adjacency bitmasks
__device__ unsigned g_union[NN * WPRP];     // union pattern
__device__ float    g_dinv[3][NN];          // D^{-1/2} per meta-path
__device__ float    g_dinvu[NN];            // D^{-1/2} for union pattern
__device__ float    g_XWs[3][NN * DOUT];    // dinv[k][i] * (features @ W_gnn[k])[i]
__device__ float    g_fs[NN * DOUT];        // dinvu[i] * f_meta[i]
__device__ float    g_atta[NN * 4];         // a[i,k] (padded stride 4)
__device__ float    g_attb[NN * 4];         // b[j,k]

// spread 8 bits to every 4th position (bit a -> bit 4a)
__device__ __forceinline__ unsigned spread8(unsigned x) {
    x = (x | (x << 12)) & 0x000F000Fu;
    x = (x | (x << 6))  & 0x03030303u;
    x = (x | (x << 3))  & 0x11111111u;
    return x;
}

// ---------------------------------------------------------------------------
// K1: warp per (row, chunk-pair).  Per chunk: one coalesced 512B LDG.128,
// 4 ballots, lanes 0..3 pack one mask word each via Morton spread, 16B store.
// No smem, no syncthreads, one-shot warps.
// ---------------------------------------------------------------------------
__global__ void k_bits(const float4* __restrict__ adj4) {
    int gw = (blockIdx.x * 256 + threadIdx.x) >> 5;   // global warp
    int lane = threadIdx.x & 31;
    if (gw >= 3 * NN * 20) return;                    // uniform per warp
    int r = gw / 20;                                  // r = k*NN + i
    int cp = gw - r * 20;                             // chunk pair 0..19
    const float4* rp = adj4 + (size_t)r * 1250;

    float4 v[2];
    #pragma unroll
    for (int h = 0; h < 2; h++) {
        int f = (cp * 2 + h) * 32 + lane;
        v[h] = (f < 1250) ? __ldcs(rp + f) : make_float4(0.f, 0.f, 0.f, 0.f);
    }
    #pragma unroll
    for (int h = 0; h < 2; h++) {
        int chunk = cp * 2 + h;
        unsigned b0 = __ballot_sync(0xffffffffu, v[h].x != 0.f);
        unsigned b1 = __ballot_sync(0xffffffffu, v[h].y != 0.f);
        unsigned b2 = __ballot_sync(0xffffffffu, v[h].z != 0.f);
        unsigned b3 = __ballot_sync(0xffffffffu, v[h].w != 0.f);
        if (lane < 4) {
            int sh = 8 * lane;
            unsigned word = spread8((b0 >> sh) & 0xFFu)
                          | (spread8((b1 >> sh) & 0xFFu) << 1)
                          | (spread8((b2 >> sh) & 0xFFu) << 2)
                          | (spread8((b3 >> sh) & 0xFFu) << 3);
            ((unsigned*)g_bits)[(size_t)r * WPRP + chunk * 4 + lane] = word;
        }
    }
}

// ---------------------------------------------------------------------------
// K2: union + degrees + dinv (masks are L2-resident).  Block per row, 160 thr.
// ---------------------------------------------------------------------------
__global__ void k_deg() {
    int i = blockIdx.x;
    int t = threadIdx.x;                     // 160 threads
    __shared__ int s_cnt[4];
    if (t < 4) s_cnt[t] = 0;
    __syncthreads();
    unsigned b0 = g_bits[0][i * WPRP + t];
    unsigned b1 = g_bits[1][i * WPRP + t];
    unsigned b2 = g_bits[2][i * WPRP + t];
    unsigned u = b0 | b1 | b2;
    g_union[i * WPRP + t] = u;
    if (t < WPR) {
        if (b0) atomicAdd(&s_cnt[0], __popc(b0));
        if (b1) atomicAdd(&s_cnt[1], __popc(b1));
        if (b2) atomicAdd(&s_cnt[2], __popc(b2));
        if (u)  atomicAdd(&s_cnt[3], __popc(u));
    }
    __syncthreads();
    if (t < 3) g_dinv[t][i] = rsqrtf((float)(s_cnt[t] + 1));
    if (t == 3) g_dinvu[i] = rsqrtf((float)(s_cnt[3] + 1));
}

// ---------------------------------------------------------------------------
// K3: XWs[k][i] = dinv[k][i] * (features[i] @ W_gnn[k]).  Register tile.
// ---------------------------------------------------------------------------
__global__ void k_xw(const float* __restrict__ feat, const float* __restrict__ W) {
    __shared__ float sf[16 * 512];             // 32 KB
    int i0 = blockIdx.x * 16;
    for (int x = threadIdx.x; x < 16 * 128; x += 192) {
        int r = x >> 7, c = x & 127;
        int gi = i0 + r;
        float4 v = make_float4(0.f, 0.f, 0.f, 0.f);
        if (gi < NN) v = ((const float4*)feat)[(size_t)gi * 128 + c];
        ((float4*)sf)[x] = v;
    }
    __syncthreads();

    int t = threadIdx.x;
    int o = t & 15;
    int k = (t >> 4) % 3;
    int rq = t / 48;                           // 0..3
    const float* wp = W + k * (512 * 16) + o;
    const float* f0 = sf + (rq * 4 + 0) * 512;
    const float* f1 = f0 + 512;
    const float* f2 = f1 + 512;
    const float* f3 = f2 + 512;
    float a0 = 0.f, a1 = 0.f, a2 = 0.f, a3 = 0.f;
    #pragma unroll 4
    for (int d = 0; d < 512; d += 4) {
        float w0 = wp[(d + 0) * 16];
        float w1 = wp[(d + 1) * 16];
        float w2 = wp[(d + 2) * 16];
        float w3 = wp[(d + 3) * 16];
        float4 x0 = *(const float4*)(f0 + d);
        float4 x1 = *(const float4*)(f1 + d);
        float4 x2 = *(const float4*)(f2 + d);
        float4 x3 = *(const float4*)(f3 + d);
        a0 = fmaf(x0.x, w0, fmaf(x0.y, w1, fmaf(x0.z, w2, fmaf(x0.w, w3, a0))));
        a1 = fmaf(x1.x, w0, fmaf(x1.y, w1, fmaf(x1.z, w2, fmaf(x1.w, w3, a1))));
        a2 = fmaf(x2.x, w0, fmaf(x2.y, w1, fmaf(x2.z, w2, fmaf(x2.w, w3, a2))));
        a3 = fmaf(x3.x, w0, fmaf(x3.y, w1, fmaf(x3.z, w2, fmaf(x3.w, w3, a3))));
    }
    int gi = i0 + rq * 4;
    if (gi + 0 < NN) g_XWs[k][(gi + 0) * DOUT + o] = a0 * g_dinv[k][gi + 0];
    if (gi + 1 < NN) g_XWs[k][(gi + 1) * DOUT + o] = a1 * g_dinv[k][gi + 1];
    if (gi + 2 < NN) g_XWs[k][(gi + 2) * DOUT + o] = a2 * g_dinv[k][gi + 2];
    if (gi + 3 < NN) g_XWs[k][(gi + 3) * DOUT + o] = a3 * g_dinv[k][gi + 3];
}

// ---------------------------------------------------------------------------
// Parallel list build: 5 word-chunks scanned on NT/32 warps concurrently,
// 5-element level-2 scan, then offset emit.
// ---------------------------------------------------------------------------
template <int NT>
__device__ __forceinline__ void build_list2(const unsigned* __restrict__ src, int lt,
                                            unsigned* s_w, int* s_base, int* s_csum,
                                            int* s_list, int* s_n) {
    for (int w = lt; w < WPRP; w += NT) {
        unsigned m = (w < WPR) ? src[w] : 0u;
        s_w[w] = m;
    }
    __syncthreads();
    int warp = lt >> 5, lane = lt & 31;
    const int NW = NT / 32;
    for (int ch = warp; ch < 5; ch += NW) {
        int w = ch * 32 + lane;
        int c = __popc(s_w[w]);
        int x = c;
        #pragma unroll
        for (int off = 1; off < 32; off <<= 1) {
            int y = __shfl_up_sync(0xffffffffu, x, off);
            if (lane >= off) x += y;
        }
        s_base[w] = x - c;
        if (lane == 31) s_csum[ch] = x;
    }
    __syncthreads();
    if (lt < 32) {
        int v = (lane < 5) ? s_csum[lane] : 0;
        int x = v;
        #pragma unroll
        for (int off = 1; off < 8; off <<= 1) {
            int y = __shfl_up_sync(0xffffffffu, x, off);
            if (lane >= off) x += y;
        }
        if (lane < 5) s_csum[lane] = x - v;       // exclusive chunk offsets
        if (lane == 4) *s_n = x;                  // total
    }
    __syncthreads();
    for (int w = lt; w < WPR; w += NT) {
        unsigned m = s_w[w];
        int base = s_base[w] + s_csum[w >> 5];
        int jb = w * 32;
        while (m) {
            int b = __ffs(m) - 1; m &= m - 1;
            s_list[base++] = jb + b;
        }
    }
    __syncthreads();
}

// float4 gather-accumulate over list, SUBS parallel streams, 2-deep pipeline.
template <int SUBS>
__device__ __forceinline__ float4 gather4(const float4* __restrict__ X4,
                                          const int* __restrict__ list,
                                          int E, int sub, int d4) {
    float4 a0 = make_float4(0.f, 0.f, 0.f, 0.f);
    float4 a1 = make_float4(0.f, 0.f, 0.f, 0.f);
    int e = sub;
    for (; e + SUBS < E; e += 2 * SUBS) {
        int j0 = list[e], j1 = list[e + SUBS];
        float4 v0 = X4[j0 * 4 + d4];
        float4 v1 = X4[j1 * 4 + d4];
        a0.x += v0.x; a0.y += v0.y; a0.z += v0.z; a0.w += v0.w;
        a1.x += v1.x; a1.y += v1.y; a1.z += v1.z; a1.w += v1.w;
    }
    if (e < E) {
        float4 v = X4[list[e] * 4 + d4];
        a0.x += v.x; a0.y += v.y; a0.z += v.z; a0.w += v.w;
    }
    a0.x += a1.x; a0.y += a1.y; a0.z += a1.z; a0.w += a1.w;
    return a0;
}

// Reduce within warp (8 subs x float4) -> s_part[warp][16].
__device__ __forceinline__ void reduce4(float4 acc, int lane, int warp, int d4,
                                        float (*s_part)[16]) {
    #pragma unroll
    for (int off = 4; off < 32; off <<= 1) {
        acc.x += __shfl_xor_sync(0xffffffffu, acc.x, off);
        acc.y += __shfl_xor_sync(0xffffffffu, acc.y, off);
        acc.z += __shfl_xor_sync(0xffffffffu, acc.z, off);
        acc.w += __shfl_xor_sync(0xffffffffu, acc.w, off);
    }
    if (lane < 4) {
        s_part[warp][d4 * 4 + 0] = acc.x;
        s_part[warp][d4 * 4 + 1] = acc.y;
        s_part[warp][d4 * 4 + 2] = acc.z;
        s_part[warp][d4 * 4 + 3] = acc.w;
    }
}

// ---------------------------------------------------------------------------
// K4: 3 meta-path GCN convs (warpgroup per k) + max -> f_meta, scaled f_s,
// attention projections (one warp per k). Block per row, 384 threads.
// ---------------------------------------------------------------------------
__global__ void k_hatt(const float* __restrict__ bgnn, const float* __restrict__ attw,
                       float* __restrict__ fmeta) {
    int i = blockIdx.x;
    int t = threadIdx.x;
    int k = t >> 7;               // warpgroup = meta-path
    int lt = t & 127;
    int lane = lt & 31, warp = lt >> 5;
    int d4 = lt & 3, sub = lt >> 2;

    __shared__ unsigned s_w[3][WPRP];
    __shared__ int s_base[3][WPRP];
    __shared__ int s_csum[3][8];
    __shared__ int s_list[3][320];
    __shared__ int s_n[3];
    __shared__ float s_part[3][4][16];
    __shared__ float s_h[3][16];
    __shared__ float s_best[16];

    build_list2<128>(&g_bits[k][i * WPRP], lt, s_w[k], s_base[k], s_csum[k],
                     s_list[k], &s_n[k]);

    float4 acc = gather4<32>((const float4*)g_XWs[k], s_list[k], s_n[k], sub, d4);
    reduce4(acc, lane, warp, d4, s_part[k]);
    __syncthreads();

    if (lt < 16) {
        const float* Xs = g_XWs[k];
        float s = s_part[k][0][lt] + s_part[k][1][lt] +
                  s_part[k][2][lt] + s_part[k][3][lt];
        float di = g_dinv[k][i];
        s_h[k][lt] = fmaf(di, s + Xs[i * DOUT + lt], bgnn[k * 16 + lt]);
    }
    __syncthreads();

    if (t < 16) {
        float best = fmaxf(s_h[0][t], fmaxf(s_h[1][t], s_h[2][t]));
        s_best[t] = best;
        fmeta[i * DOUT + t] = best;
        g_fs[i * DOUT + t] = g_dinvu[i] * best;
    }
    __syncthreads();

    if (t < 96) {
        int kk = t >> 5;
        int l = t & 31;
        float best = (l < 16) ? s_best[l] : 0.f;
        float va = (l < 16) ? best * attw[kk * 32 + l] : 0.f;
        float vb = (l < 16) ? best * attw[kk * 32 + 16 + l] : 0.f;
        #pragma unroll
        for (int off = 8; off >= 1; off >>= 1) {
            va += __shfl_xor_sync(0xffffffffu, va, off);
            vb += __shfl_xor_sync(0xffffffffu, vb, off);
        }
        if (l == 0) { g_atta[i * 4 + kk] = va; g_attb[i * 4 + kk] = vb; }
    }
}

// ---------------------------------------------------------------------------
// K5: fused (a) t = norm_meta @ f_meta + predictions, (b) full A_meta row
// write.  Block per row, 256 threads.
// ---------------------------------------------------------------------------
__global__ void k_post(const float* __restrict__ Wf, const float* __restrict__ bf,
                       float* __restrict__ pred, float* __restrict__ Am) {
    int i = blockIdx.x;
    int t = threadIdx.x;                       // 256 threads
    int lane = t & 31, warp = t >> 5;
    int d4 = t & 3, sub = t >> 2;              // 64 subs
    __shared__ unsigned s_w[WPRP];
    __shared__ int s_base[WPRP];
    __shared__ int s_csum[8];
    __shared__ int s_list[384];
    __shared__ int s_n;
    __shared__ float s_part[8][16];
    __shared__ float s_t[16];
    __shared__ float s_vals[384];
    __shared__ unsigned s_b0[WPR], s_b1[WPR], s_b2[WPR];

    for (int w = t; w < WPR; w += 256) {
        s_b0[w] = g_bits[0][i * WPRP + w];
        s_b1[w] = g_bits[1][i * WPRP + w];
        s_b2[w] = g_bits[2][i * WPRP + w];
    }

    build_list2<256>(g_union + i * WPRP, t, s_w, s_base, s_csum, s_list, &s_n);
    int E = s_n;

    // ---- (a) union SpMM ----
    float4 acc = gather4<64>((const float4*)g_fs, s_list, E, sub, d4);
    reduce4(acc, lane, warp, d4, s_part);
    __syncthreads();
    if (t < 16) {
        float di = g_dinvu[i];
        float s = 0.f;
        #pragma unroll
        for (int wq = 0; wq < 8; wq++) s += s_part[wq][t];
        s_t[t] = di * (s + g_fs[i * DOUT + t]);
    }
    __syncthreads();
    if (t < NCLS) {
        float p = bf[t];
        #pragma unroll
        for (int o = 0; o < DOUT; o++)
            p = fmaf(s_t[o], Wf[o * NCLS + t], p);
        pred[i * NCLS + t] = p;
    }

    // ---- (b) per-nonzero attention values ----
    float4 A = *(const float4*)&g_atta[i * 4];
    for (int e = t; e < E; e += 256) {
        int j = s_list[e];
        float4 B = *(const float4*)&g_attb[j * 4];
        float s0 = __expf(fmaxf(A.x + B.x, 0.f));
        float s1 = __expf(fmaxf(A.y + B.y, 0.f));
        float s2 = __expf(fmaxf(A.z + B.z, 0.f));
        int w = j >> 5, b = j & 31;
        float num = (((s_b0[w] >> b) & 1u) ? s0 : 0.f) +
                    (((s_b1[w] >> b) & 1u) ? s1 : 0.f) +
                    (((s_b2[w] >> b) & 1u) ? s2 : 0.f);
        s_vals[e] = __fdividef(num, s0 + s1 + s2);
    }
    __syncthreads();

    // ---- (c) full A_meta row write (streaming) ----
    float4* arow = (float4*)(Am + (size_t)i * NN);
    for (int q = t; q < 1250; q += 256) {
        int w = q >> 3;
        unsigned mw = s_w[w];
        unsigned nib = (mw >> ((q & 7) * 4)) & 0xFu;
        float4 o = make_float4(0.f, 0.f, 0.f, 0.f);
        if (nib) {
            int base = s_base[w] + s_csum[w >> 5];
            int bsh = (q & 7) * 4;
            float v[4] = {0.f, 0.f, 0.f, 0.f};
            #pragma unroll
            for (int c = 0; c < 4; c++) {
                if ((nib >> c) & 1u) {
                    int b = bsh + c;
                    int idx = base + __popc(mw & ((1u << b) - 1u));
                    v[c] = s_vals[idx];
                }
            }
            o = make_float4(v[0], v[1], v[2], v[3]);
        }
        __stcs(arow + q, o);
    }
}

// ---------------------------------------------------------------------------
extern "C" void kernel_launch(void* const* d_in, const int* in_sizes, int n_in,
                              void* d_out, int out_size) {
    const float* features = (const float*)d_in[0];
    const float* adj      = (const float*)d_in[1];
    const float* W_gnn    = (const float*)d_in[2];
    const float* b_gnn    = (const float*)d_in[3];
    const float* att_w    = (const float*)d_in[4];
    const float* W_final  = (const float*)d_in[5];
    const float* b_final  = (const float*)d_in[6];

    float* out   = (float*)d_out;
    float* fmeta = out;                                        // [5000,16]
    float* Ameta = out + (size_t)NN * DOUT;                    // [5000,5000]
    float* pred  = out + (size_t)NN * DOUT + (size_t)NN * NN;  // [5000,100]

    k_bits<<<(3 * NN * 20) / 8, 256>>>((const float4*)adj);    // 37500 blocks
    k_deg<<<NN, 160>>>();
    k_xw<<<(NN + 15) / 16, 192>>>(features, W_gnn);
    k_hatt<<<NN, 384>>>(b_gnn, att_w, fmeta);
    k_post<<<NN, 256>>>(W_final, b_final, pred, Ameta);
}

// round 15
// speedup vs baseline: 1.0211x; 1.0211x over previous
#include <cuda_runtime.h>
#include <math.h>

// ---------------------------------------------------------------------------
// HSGNN forward, GB300.  Sparse-bitmask pipeline, 3 kernels.
// K1: fused prep (pass-1 at the measured ~4 TB/s read ceiling).
// K2: union-list membership-masked triple gather (1 list build, not 3).
// K3: union SpMM + predictions + full A_meta row write.
// ---------------------------------------------------------------------------

#define NN 5000
#define WPR 157      // ceil(5000/32) words per bitmask row
#define WPRP 160     // padded words per row (= 5 chunks of 32)
#define DOUT 16
#define NCLS 100

__device__ unsigned g_bits[3][NN * WPRP];   // per-meta-path adjacency bitmasks
__device__ float    g_dinv[3][NN];          // D^{-1/2} per meta-path
__device__ float    g_dinvu[NN];            // D^{-1/2} for union pattern
__device__ float    g_XWs[3][NN * DOUT];    // dinv[k][i] * (features @ W_gnn[k])[i]
__device__ float    g_fs[NN * DOUT];        // dinvu[i] * f_meta[i]
__device__ float    g_atta[NN * 4];         // a[i,k] (padded stride 4)
__device__ float    g_attb[NN * 4];         // b[j,k]

// ---------------------------------------------------------------------------
// K1: per row i — 3 sequential 5-deep load batches; nibble -> shuffle-OR ->
// one STS per word; XW fused after.  256 threads.
// ---------------------------------------------------------------------------
__global__ void k_prep(const float* __restrict__ adj, const float* __restrict__ feat,
                       const float* __restrict__ W) {
    int i = blockIdx.x;
    int t = threadIdx.x;                       // 256 threads
    __shared__ float s_f[512];
    __shared__ unsigned s_b[3][WPRP + 3];
    __shared__ int s_cnt[4];
    __shared__ float s_xw[48][4];
    __shared__ float s_dinv[3];

    if (t < 4) s_cnt[t] = 0;
    if (t < 128) ((float4*)s_f)[t] = ((const float4*)(feat + (size_t)i * 512))[t];

    int bsh = (t & 7) * 4;                     // nibble position within word

    #pragma unroll
    for (int k = 0; k < 3; k++) {
        const float4* rp = (const float4*)(adj + ((size_t)k * NN + i) * NN);
        float4 v[5];
        #pragma unroll
        for (int u = 0; u < 5; u++) {
            int q = t + 256 * u;
            if (q < 1250) v[u] = __ldcs(rp + q);
            else          v[u] = make_float4(0.f, 0.f, 0.f, 0.f);
        }
        #pragma unroll
        for (int u = 0; u < 5; u++) {
            int q = t + 256 * u;
            unsigned nb = (v[u].x != 0.f ? 1u : 0u) | (v[u].y != 0.f ? 2u : 0u) |
                          (v[u].z != 0.f ? 4u : 0u) | (v[u].w != 0.f ? 8u : 0u);
            unsigned x = nb << bsh;
            x |= __shfl_xor_sync(0xffffffffu, x, 1);
            x |= __shfl_xor_sync(0xffffffffu, x, 2);
            x |= __shfl_xor_sync(0xffffffffu, x, 4);
            if ((t & 7) == 0) s_b[k][q >> 3] = x;
        }
    }
    __syncthreads();

    // XW partials: 192 threads = (part:4) x (k:3) x (o:16), 128 dims each
    if (t < 192) {
        int o = t & 15, k = (t >> 4) % 3, part = t / 48;
        const float* wp = W + k * (512 * 16) + o;
        const float* fp = s_f + part * 128;
        float a = 0.f;
        #pragma unroll 8
        for (int d = 0; d < 128; d++)
            a = fmaf(fp[d], wp[(part * 128 + d) * 16], a);
        s_xw[k * 16 + o][part] = a;
    }
    if (t < WPR) {
        unsigned b0 = s_b[0][t], b1 = s_b[1][t], b2 = s_b[2][t];
        unsigned u = b0 | b1 | b2;
        g_bits[0][i * WPRP + t] = b0;
        g_bits[1][i * WPRP + t] = b1;
        g_bits[2][i * WPRP + t] = b2;
        if (b0) atomicAdd(&s_cnt[0], __popc(b0));
        if (b1) atomicAdd(&s_cnt[1], __popc(b1));
        if (b2) atomicAdd(&s_cnt[2], __popc(b2));
        if (u)  atomicAdd(&s_cnt[3], __popc(u));
    } else if (t < WPRP) {
        g_bits[0][i * WPRP + t] = 0;
        g_bits[1][i * WPRP + t] = 0;
        g_bits[2][i * WPRP + t] = 0;
    }
    __syncthreads();
    if (t < 3) {
        float dv = rsqrtf((float)(s_cnt[t] + 1));
        s_dinv[t] = dv;
        g_dinv[t][i] = dv;
    }
    if (t == 3) g_dinvu[i] = rsqrtf((float)(s_cnt[3] + 1));
    __syncthreads();
    if (t < 48) {
        int k = t >> 4, o = t & 15;
        float s = s_xw[t][0] + s_xw[t][1] + s_xw[t][2] + s_xw[t][3];
        g_XWs[k][i * DOUT + o] = s * s_dinv[k];
    }
}

// ---------------------------------------------------------------------------
// K2: one union list + membership-masked triple gather.  Block per row,
// 384 threads (12 warps; 96 gather subs).
// ---------------------------------------------------------------------------
__global__ void k_hatt(const float* __restrict__ bgnn, const float* __restrict__ attw,
                       float* __restrict__ fmeta) {
    int i = blockIdx.x;
    int t = threadIdx.x;                       // 384 threads
    int lane = t & 31, warp = t >> 5;          // 12 warps
    int d4 = t & 3, sub = t >> 2;              // 96 subs

    __shared__ unsigned s_b0[WPRP], s_b1[WPRP], s_b2[WPRP], s_w[WPRP];
    __shared__ int s_base[WPRP];
    __shared__ int s_csum[8];
    __shared__ int s_list[384];
    __shared__ int s_n;
    __shared__ float s_part[3][12][16];
    __shared__ float s_h[3][16];
    __shared__ float s_best[16];

    // stage masks + union
    for (int w = t; w < WPRP; w += 384) {
        unsigned b0 = g_bits[0][i * WPRP + w];
        unsigned b1 = g_bits[1][i * WPRP + w];
        unsigned b2 = g_bits[2][i * WPRP + w];
        s_b0[w] = b0; s_b1[w] = b1; s_b2[w] = b2;
        s_w[w] = b0 | b1 | b2;
    }
    __syncthreads();

    // fully-parallel scan: warps 0..4 own one 32-word chunk each
    if (warp < 5) {
        int w = warp * 32 + lane;
        int c = __popc(s_w[w]);
        int x = c;
        #pragma unroll
        for (int off = 1; off < 32; off <<= 1) {
            int y = __shfl_up_sync(0xffffffffu, x, off);
            if (lane >= off) x += y;
        }
        s_base[w] = x - c;
        if (lane == 31) s_csum[warp] = x;
    }
    __syncthreads();
    if (t < 32) {
        int v = (lane < 5) ? s_csum[lane] : 0;
        int x = v;
        #pragma unroll
        for (int off = 1; off < 8; off <<= 1) {
            int y = __shfl_up_sync(0xffffffffu, x, off);
            if (lane >= off) x += y;
        }
        if (lane < 5) s_csum[lane] = x - v;
        if (lane == 4) s_n = x;
    }
    __syncthreads();
    for (int w = t; w < WPR; w += 384) {
        unsigned m = s_w[w];
        int base = s_base[w] + s_csum[w >> 5];
        int jb = w * 32;
        while (m) {
            int b = __ffs(m) - 1; m &= m - 1;
            s_list[base++] = jb + b;
        }
    }
    __syncthreads();
    int E = s_n;

    // membership-masked triple gather over the union list
    const float4* X0 = (const float4*)g_XWs[0];
    const float4* X1 = (const float4*)g_XWs[1];
    const float4* X2 = (const float4*)g_XWs[2];
    float4 a0 = make_float4(0.f, 0.f, 0.f, 0.f);
    float4 a1 = a0, a2 = a0;
    for (int e = sub; e < E; e += 96) {
        int j = s_list[e];
        int w = j >> 5, b = j & 31;
        unsigned m0 = s_b0[w], m1 = s_b1[w], m2 = s_b2[w];
        if ((m0 >> b) & 1u) {
            float4 v = X0[j * 4 + d4];
            a0.x += v.x; a0.y += v.y; a0.z += v.z; a0.w += v.w;
        }
        if ((m1 >> b) & 1u) {
            float4 v = X1[j * 4 + d4];
            a1.x += v.x; a1.y += v.y; a1.z += v.z; a1.w += v.w;
        }
        if ((m2 >> b) & 1u) {
            float4 v = X2[j * 4 + d4];
            a2.x += v.x; a2.y += v.y; a2.z += v.z; a2.w += v.w;
        }
    }
    // reduce 8 subs per warp for each of the 3 accumulators
    #pragma unroll
    for (int off = 4; off < 32; off <<= 1) {
        a0.x += __shfl_xor_sync(0xffffffffu, a0.x, off);
        a0.y += __shfl_xor_sync(0xffffffffu, a0.y, off);
        a0.z += __shfl_xor_sync(0xffffffffu, a0.z, off);
        a0.w += __shfl_xor_sync(0xffffffffu, a0.w, off);
        a1.x += __shfl_xor_sync(0xffffffffu, a1.x, off);
        a1.y += __shfl_xor_sync(0xffffffffu, a1.y, off);
        a1.z += __shfl_xor_sync(0xffffffffu, a1.z, off);
        a1.w += __shfl_xor_sync(0xffffffffu, a1.w, off);
        a2.x += __shfl_xor_sync(0xffffffffu, a2.x, off);
        a2.y += __shfl_xor_sync(0xffffffffu, a2.y, off);
        a2.z += __shfl_xor_sync(0xffffffffu, a2.z, off);
        a2.w += __shfl_xor_sync(0xffffffffu, a2.w, off);
    }
    if (lane < 4) {
        int o = d4 * 4;
        s_part[0][warp][o + 0] = a0.x; s_part[0][warp][o + 1] = a0.y;
        s_part[0][warp][o + 2] = a0.z; s_part[0][warp][o + 3] = a0.w;
        s_part[1][warp][o + 0] = a1.x; s_part[1][warp][o + 1] = a1.y;
        s_part[1][warp][o + 2] = a1.z; s_part[1][warp][o + 3] = a1.w;
        s_part[2][warp][o + 0] = a2.x; s_part[2][warp][o + 1] = a2.y;
        s_part[2][warp][o + 2] = a2.z; s_part[2][warp][o + 3] = a2.w;
    }
    __syncthreads();

    if (t < 48) {
        int k = t >> 4, o = t & 15;
        float s = 0.f;
        #pragma unroll
        for (int w = 0; w < 12; w++) s += s_part[k][w][o];
        float di = g_dinv[k][i];
        s_h[k][o] = fmaf(di, s + g_XWs[k][i * DOUT + o], bgnn[k * 16 + o]);
    }
    __syncthreads();

    if (t < 16) {
        float best = fmaxf(s_h[0][t], fmaxf(s_h[1][t], s_h[2][t]));
        s_best[t] = best;
        fmeta[i * DOUT + t] = best;
        g_fs[i * DOUT + t] = g_dinvu[i] * best;
    }
    __syncthreads();

    if (t < 96) {
        int kk = t >> 5;
        int l = t & 31;
        float best = (l < 16) ? s_best[l] : 0.f;
        float va = (l < 16) ? best * attw[kk * 32 + l] : 0.f;
        float vb = (l < 16) ? best * attw[kk * 32 + 16 + l] : 0.f;
        #pragma unroll
        for (int off = 8; off >= 1; off >>= 1) {
            va += __shfl_xor_sync(0xffffffffu, va, off);
            vb += __shfl_xor_sync(0xffffffffu, vb, off);
        }
        if (l == 0) { g_atta[i * 4 + kk] = va; g_attb[i * 4 + kk] = vb; }
    }
}

// float4 gather-accumulate over list, SUBS parallel streams, 2-deep pipeline.
template <int SUBS>
__device__ __forceinline__ float4 gather4(const float4* __restrict__ X4,
                                          const int* __restrict__ list,
                                          int E, int sub, int d4) {
    float4 a0 = make_float4(0.f, 0.f, 0.f, 0.f);
    float4 a1 = make_float4(0.f, 0.f, 0.f, 0.f);
    int e = sub;
    for (; e + SUBS < E; e += 2 * SUBS) {
        int j0 = list[e], j1 = list[e + SUBS];
        float4 v0 = X4[j0 * 4 + d4];
        float4 v1 = X4[j1 * 4 + d4];
        a0.x += v0.x; a0.y += v0.y; a0.z += v0.z; a0.w += v0.w;
        a1.x += v1.x; a1.y += v1.y; a1.z += v1.z; a1.w += v1.w;
    }
    if (e < E) {
        float4 v = X4[list[e] * 4 + d4];
        a0.x += v.x; a0.y += v.y; a0.z += v.z; a0.w += v.w;
    }
    a0.x += a1.x; a0.y += a1.y; a0.z += a1.z; a0.w += a1.w;
    return a0;
}

// ---------------------------------------------------------------------------
// K3: fused (a) t = norm_meta @ f_meta + predictions, (b) full A_meta row
// write.  Block per row, 256 threads.  Union computed from staged masks.
// ---------------------------------------------------------------------------
__global__ void k_post(const float* __restrict__ Wf, const float* __restrict__ bf,
                       float* __restrict__ pred, float* __restrict__ Am) {
    int i = blockIdx.x;
    int t = threadIdx.x;                       // 256 threads
    int lane = t & 31, warp = t >> 5;
    int d4 = t & 3, sub = t >> 2;              // 64 subs
    __shared__ unsigned s_b0[WPRP], s_b1[WPRP], s_b2[WPRP], s_w[WPRP];
    __shared__ int s_base[WPRP];
    __shared__ int s_csum[8];
    __shared__ int s_list[384];
    __shared__ int s_n;
    __shared__ float s_part[8][16];
    __shared__ float s_t[16];
    __shared__ float s_vals[384];

    for (int w = t; w < WPRP; w += 256) {
        unsigned b0 = g_bits[0][i * WPRP + w];
        unsigned b1 = g_bits[1][i * WPRP + w];
        unsigned b2 = g_bits[2][i * WPRP + w];
        s_b0[w] = b0; s_b1[w] = b1; s_b2[w] = b2;
        s_w[w] = b0 | b1 | b2;
    }
    __syncthreads();

    if (warp < 5) {
        int w = warp * 32 + lane;
        int c = __popc(s_w[w]);
        int x = c;
        #pragma unroll
        for (int off = 1; off < 32; off <<= 1) {
            int y = __shfl_up_sync(0xffffffffu, x, off);
            if (lane >= off) x += y;
        }
        s_base[w] = x - c;
        if (lane == 31) s_csum[warp] = x;
    }
    __syncthreads();
    if (t < 32) {
        int v = (lane < 5) ? s_csum[lane] : 0;
        int x = v;
        #pragma unroll
        for (int off = 1; off < 8; off <<= 1) {
            int y = __shfl_up_sync(0xffffffffu, x, off);
            if (lane >= off) x += y;
        }
        if (lane < 5) s_csum[lane] = x - v;
        if (lane == 4) s_n = x;
    }
    __syncthreads();
    for (int w = t; w < WPR; w += 256) {
        unsigned m = s_w[w];
        int base = s_base[w] + s_csum[w >> 5];
        int jb = w * 32;
        while (m) {
            int b = __ffs(m) - 1; m &= m - 1;
            s_list[base++] = jb + b;
        }
    }
    __syncthreads();
    int E = s_n;

    // ---- (a) union SpMM ----
    float4 acc = gather4<64>((const float4*)g_fs, s_list, E, sub, d4);
    #pragma unroll
    for (int off = 4; off < 32; off <<= 1) {
        acc.x += __shfl_xor_sync(0xffffffffu, acc.x, off);
        acc.y += __shfl_xor_sync(0xffffffffu, acc.y, off);
        acc.z += __shfl_xor_sync(0xffffffffu, acc.z, off);
        acc.w += __shfl_xor_sync(0xffffffffu, acc.w, off);
    }
    if (lane < 4) {
        s_part[warp][d4 * 4 + 0] = acc.x;
        s_part[warp][d4 * 4 + 1] = acc.y;
        s_part[warp][d4 * 4 + 2] = acc.z;
        s_part[warp][d4 * 4 + 3] = acc.w;
    }
    __syncthreads();
    if (t < 16) {
        float di = g_dinvu[i];
        float s = 0.f;
        #pragma unroll
        for (int wq = 0; wq < 8; wq++) s += s_part[wq][t];
        s_t[t] = di * (s + g_fs[i * DOUT + t]);
    }
    __syncthreads();
    if (t < NCLS) {
        float p = bf[t];
        #pragma unroll
        for (int o = 0; o < DOUT; o++)
            p = fmaf(s_t[o], Wf[o * NCLS + t], p);
        pred[i * NCLS + t] = p;
    }

    // ---- (b) per-nonzero attention values ----
    float4 A = *(const float4*)&g_atta[i * 4];
    for (int e = t; e < E; e += 256) {
        int j = s_list[e];
        float4 B = *(const float4*)&g_attb[j * 4];
        float s0 = __expf(fmaxf(A.x + B.x, 0.f));
        float s1 = __expf(fmaxf(A.y + B.y, 0.f));
        float s2 = __expf(fmaxf(A.z + B.z, 0.f));
        int w = j >> 5, b = j & 31;
        float num = (((s_b0[w] >> b) & 1u) ? s0 : 0.f) +
                    (((s_b1[w] >> b) & 1u) ? s1 : 0.f) +
                    (((s_b2[w] >> b) & 1u) ? s2 : 0.f);
        s_vals[e] = __fdividef(num, s0 + s1 + s2);
    }
    __syncthreads();

    // ---- (c) full A_meta row write (streaming) ----
    float4* arow = (float4*)(Am + (size_t)i * NN);
    for (int q = t; q < 1250; q += 256) {
        int w = q >> 3;
        unsigned mw = s_w[w];
        unsigned nib = (mw >> ((q & 7) * 4)) & 0xFu;
        float4 o = make_float4(0.f, 0.f, 0.f, 0.f);
        if (nib) {
            int base = s_base[w] + s_csum[w >> 5];
            int bsh = (q & 7) * 4;
            float v[4] = {0.f, 0.f, 0.f, 0.f};
            #pragma unroll
            for (int c = 0; c < 4; c++) {
                if ((nib >> c) & 1u) {
                    int b = bsh + c;
                    int idx = base + __popc(mw & ((1u << b) - 1u));
                    v[c] = s_vals[idx];
                }
            }
            o = make_float4(v[0], v[1], v[2], v[3]);
        }
        __stcs(arow + q, o);
    }
}

// ---------------------------------------------------------------------------
extern "C" void kernel_launch(void* const* d_in, const int* in_sizes, int n_in,
                              void* d_out, int out_size) {
    const float* features = (const float*)d_in[0];
    const float* adj      = (const float*)d_in[1];
    const float* W_gnn    = (const float*)d_in[2];
    const float* b_gnn    = (const float*)d_in[3];
    const float* att_w    = (const float*)d_in[4];
    const float* W_final  = (const float*)d_in[5];
    const float* b_final  = (const float*)d_in[6];

    float* out   = (float*)d_out;
    float* fmeta = out;                                        // [5000,16]
    float* Ameta = out + (size_t)NN * DOUT;                    // [5000,5000]
    float* pred  = out + (size_t)NN * DOUT + (size_t)NN * NN;  // [5000,100]

    k_prep<<<NN, 256>>>(adj, features, W_gnn);
    k_hatt<<<NN, 384>>>(b_gnn, att_w, fmeta);
    k_post<<<NN, 256>>>(W_final, b_final, pred, Ameta);
}

// round 16
// speedup vs baseline: 1.0425x; 1.0210x over previous
#include <cuda_runtime.h>
#include <math.h>

// ---------------------------------------------------------------------------
// HSGNN forward, GB300.  Sparse-bitmask pipeline, 3 kernels.
// K1: fused prep (at the measured ~4 TB/s read ceiling).
// K2: per-path lists, warpgroup-private named barriers (no block convoys).
// K3: union SpMM + predictions + A_meta row write (at the write ceiling).
// ---------------------------------------------------------------------------

#define NN 5000
#define WPR 157      // ceil(5000/32) words per bitmask row
#define WPRP 160     // padded words per row (= 5 chunks of 32)
#define DOUT 16
#define NCLS 100

#define GBAR(id) asm volatile("bar.sync %0, 128;" :: "r"(id) : "memory")

__device__ unsigned g_bits[3][NN * WPRP];   // per-meta-path adjacency bitmasks
__device__ float    g_dinv[3][NN];          // D^{-1/2} per meta-path
__device__ float    g_dinvu[NN];            // D^{-1/2} for union pattern
__device__ float    g_XWs[3][NN * DOUT];    // dinv[k][i] * (features @ W_gnn[k])[i]
__device__ float    g_fs[NN * DOUT];        // dinvu[i] * f_meta[i]
__device__ float    g_atta[NN * 4];         // a[i,k] (padded stride 4)
__device__ float    g_attb[NN * 4];         // b[j,k]

// ---------------------------------------------------------------------------
// K1: per row i — 3 sequential 5-deep load batches; nibble -> shuffle-OR ->
// one STS per word; XW fused after.  256 threads.
// ---------------------------------------------------------------------------
__global__ void k_prep(const float* __restrict__ adj, const float* __restrict__ feat,
                       const float* __restrict__ W) {
    int i = blockIdx.x;
    int t = threadIdx.x;                       // 256 threads
    __shared__ float s_f[512];
    __shared__ unsigned s_b[3][WPRP + 3];
    __shared__ int s_cnt[4];
    __shared__ float s_xw[48][4];
    __shared__ float s_dinv[3];

    if (t < 4) s_cnt[t] = 0;
    if (t < 128) ((float4*)s_f)[t] = ((const float4*)(feat + (size_t)i * 512))[t];

    int bsh = (t & 7) * 4;                     // nibble position within word

    #pragma unroll
    for (int k = 0; k < 3; k++) {
        const float4* rp = (const float4*)(adj + ((size_t)k * NN + i) * NN);
        float4 v[5];
        #pragma unroll
        for (int u = 0; u < 5; u++) {
            int q = t + 256 * u;
            if (q < 1250) v[u] = __ldcs(rp + q);
            else          v[u] = make_float4(0.f, 0.f, 0.f, 0.f);
        }
        #pragma unroll
        for (int u = 0; u < 5; u++) {
            int q = t + 256 * u;
            unsigned nb = (v[u].x != 0.f ? 1u : 0u) | (v[u].y != 0.f ? 2u : 0u) |
                          (v[u].z != 0.f ? 4u : 0u) | (v[u].w != 0.f ? 8u : 0u);
            unsigned x = nb << bsh;
            x |= __shfl_xor_sync(0xffffffffu, x, 1);
            x |= __shfl_xor_sync(0xffffffffu, x, 2);
            x |= __shfl_xor_sync(0xffffffffu, x, 4);
            if ((t & 7) == 0) s_b[k][q >> 3] = x;
        }
    }
    __syncthreads();

    // XW partials: 192 threads = (part:4) x (k:3) x (o:16), 128 dims each
    if (t < 192) {
        int o = t & 15, k = (t >> 4) % 3, part = t / 48;
        const float* wp = W + k * (512 * 16) + o;
        const float* fp = s_f + part * 128;
        float a = 0.f;
        #pragma unroll 8
        for (int d = 0; d < 128; d++)
            a = fmaf(fp[d], wp[(part * 128 + d) * 16], a);
        s_xw[k * 16 + o][part] = a;
    }
    if (t < WPR) {
        unsigned b0 = s_b[0][t], b1 = s_b[1][t], b2 = s_b[2][t];
        unsigned u = b0 | b1 | b2;
        g_bits[0][i * WPRP + t] = b0;
        g_bits[1][i * WPRP + t] = b1;
        g_bits[2][i * WPRP + t] = b2;
        if (b0) atomicAdd(&s_cnt[0], __popc(b0));
        if (b1) atomicAdd(&s_cnt[1], __popc(b1));
        if (b2) atomicAdd(&s_cnt[2], __popc(b2));
        if (u)  atomicAdd(&s_cnt[3], __popc(u));
    } else if (t < WPRP) {
        g_bits[0][i * WPRP + t] = 0;
        g_bits[1][i * WPRP + t] = 0;
        g_bits[2][i * WPRP + t] = 0;
    }
    __syncthreads();
    if (t < 3) {
        float dv = rsqrtf((float)(s_cnt[t] + 1));
        s_dinv[t] = dv;
        g_dinv[t][i] = dv;
    }
    if (t == 3) g_dinvu[i] = rsqrtf((float)(s_cnt[3] + 1));
    __syncthreads();
    if (t < 48) {
        int k = t >> 4, o = t & 15;
        float s = s_xw[t][0] + s_xw[t][1] + s_xw[t][2] + s_xw[t][3];
        g_XWs[k][i * DOUT + o] = s * s_dinv[k];
    }
}

// float4 gather-accumulate over list, SUBS parallel streams, 2-deep pipeline.
template <int SUBS>
__device__ __forceinline__ float4 gather4(const float4* __restrict__ X4,
                                          const int* __restrict__ list,
                                          int E, int sub, int d4) {
    float4 a0 = make_float4(0.f, 0.f, 0.f, 0.f);
    float4 a1 = make_float4(0.f, 0.f, 0.f, 0.f);
    int e = sub;
    for (; e + SUBS < E; e += 2 * SUBS) {
        int j0 = list[e], j1 = list[e + SUBS];
        float4 v0 = X4[j0 * 4 + d4];
        float4 v1 = X4[j1 * 4 + d4];
        a0.x += v0.x; a0.y += v0.y; a0.z += v0.z; a0.w += v0.w;
        a1.x += v1.x; a1.y += v1.y; a1.z += v1.z; a1.w += v1.w;
    }
    if (e < E) {
        float4 v = X4[list[e] * 4 + d4];
        a0.x += v.x; a0.y += v.y; a0.z += v.z; a0.w += v.w;
    }
    a0.x += a1.x; a0.y += a1.y; a0.z += a1.z; a0.w += a1.w;
    return a0;
}

// Reduce within warp (8 subs x float4) -> s_part[warp][16].
__device__ __forceinline__ void reduce4(float4 acc, int lane, int warp, int d4,
                                        float (*s_part)[16]) {
    #pragma unroll
    for (int off = 4; off < 32; off <<= 1) {
        acc.x += __shfl_xor_sync(0xffffffffu, acc.x, off);
        acc.y += __shfl_xor_sync(0xffffffffu, acc.y, off);
        acc.z += __shfl_xor_sync(0xffffffffu, acc.z, off);
        acc.w += __shfl_xor_sync(0xffffffffu, acc.w, off);
    }
    if (lane < 4) {
        s_part[warp][d4 * 4 + 0] = acc.x;
        s_part[warp][d4 * 4 + 1] = acc.y;
        s_part[warp][d4 * 4 + 2] = acc.z;
        s_part[warp][d4 * 4 + 3] = acc.w;
    }
}

// ---------------------------------------------------------------------------
// K2: 3 meta-path GCN convs, one 128-thread warpgroup per k, decoupled via
// NAMED barriers (no block-wide convoys until the final epilogue).
// Block per row, 384 threads.
// ---------------------------------------------------------------------------
__global__ void k_hatt(const float* __restrict__ bgnn, const float* __restrict__ attw,
                       float* __restrict__ fmeta) {
    int i = blockIdx.x;
    int t = threadIdx.x;
    int k = t >> 7;               // warpgroup = meta-path
    int lt = t & 127;
    int lane = lt & 31, warp = lt >> 5;        // warp within group (0..3)
    int d4 = lt & 3, sub = lt >> 2;
    int bar = k + 1;                           // named barrier id per group

    __shared__ unsigned s_w[3][WPRP];
    __shared__ int s_base[3][WPRP];
    __shared__ int s_csum[3][8];
    __shared__ int s_list[3][320];
    __shared__ int s_n[3];
    __shared__ float s_part[3][4][16];
    __shared__ float s_h[3][16];
    __shared__ float s_best[16];

    // ---- stage masks (group-private) ----
    for (int w = lt; w < WPRP; w += 128) {
        s_w[k][w] = (w < WPR) ? g_bits[k][i * WPRP + w] : 0u;
    }
    GBAR(bar);

    // ---- per-chunk scan: 4 warps cover 5 chunks (warp 0 does 0 and 4) ----
    for (int ch = warp; ch < 5; ch += 4) {
        int w = ch * 32 + lane;
        int c = __popc(s_w[k][w]);
        int x = c;
        #pragma unroll
        for (int off = 1; off < 32; off <<= 1) {
            int y = __shfl_up_sync(0xffffffffu, x, off);
            if (lane >= off) x += y;
        }
        s_base[k][w] = x - c;
        if (lane == 31) s_csum[k][ch] = x;
    }
    GBAR(bar);
    if (warp == 0) {
        int v = (lane < 5) ? s_csum[k][lane] : 0;
        int x = v;
        #pragma unroll
        for (int off = 1; off < 8; off <<= 1) {
            int y = __shfl_up_sync(0xffffffffu, x, off);
            if (lane >= off) x += y;
        }
        if (lane < 5) s_csum[k][lane] = x - v;
        if (lane == 4) s_n[k] = x;
    }
    GBAR(bar);
    for (int w = lt; w < WPR; w += 128) {
        unsigned m = s_w[k][w];
        int base = s_base[k][w] + s_csum[k][w >> 5];
        int jb = w * 32;
        while (m) {
            int b = __ffs(m) - 1; m &= m - 1;
            s_list[k][base++] = jb + b;
        }
    }
    GBAR(bar);

    // ---- gather + reduce (group-private) ----
    float4 acc = gather4<32>((const float4*)g_XWs[k], s_list[k], s_n[k], sub, d4);
    reduce4(acc, lane, warp, d4, s_part[k]);
    GBAR(bar);

    if (lt < 16) {
        const float* Xs = g_XWs[k];
        float s = s_part[k][0][lt] + s_part[k][1][lt] +
                  s_part[k][2][lt] + s_part[k][3][lt];
        float di = g_dinv[k][i];
        s_h[k][lt] = fmaf(di, s + Xs[i * DOUT + lt], bgnn[k * 16 + lt]);
    }
    __syncthreads();                           // only block-wide join

    if (t < 16) {
        float best = fmaxf(s_h[0][t], fmaxf(s_h[1][t], s_h[2][t]));
        s_best[t] = best;
        fmeta[i * DOUT + t] = best;
        g_fs[i * DOUT + t] = g_dinvu[i] * best;
    }
    __syncthreads();

    if (t < 96) {
        int kk = t >> 5;
        int l = t & 31;
        float best = (l < 16) ? s_best[l] : 0.f;
        float va = (l < 16) ? best * attw[kk * 32 + l] : 0.f;
        float vb = (l < 16) ? best * attw[kk * 32 + 16 + l] : 0.f;
        #pragma unroll
        for (int off = 8; off >= 1; off >>= 1) {
            va += __shfl_xor_sync(0xffffffffu, va, off);
            vb += __shfl_xor_sync(0xffffffffu, vb, off);
        }
        if (l == 0) { g_atta[i * 4 + kk] = va; g_attb[i * 4 + kk] = vb; }
    }
}

// ---------------------------------------------------------------------------
// K3: fused (a) t = norm_meta @ f_meta + predictions, (b) full A_meta row
// write.  Block per row, 256 threads.  Union computed from staged masks.
// ---------------------------------------------------------------------------
__global__ void k_post(const float* __restrict__ Wf, const float* __restrict__ bf,
                       float* __restrict__ pred, float* __restrict__ Am) {
    int i = blockIdx.x;
    int t = threadIdx.x;                       // 256 threads
    int lane = t & 31, warp = t >> 5;
    int d4 = t & 3, sub = t >> 2;              // 64 subs
    __shared__ unsigned s_b0[WPRP], s_b1[WPRP], s_b2[WPRP], s_w[WPRP];
    __shared__ int s_base[WPRP];
    __shared__ int s_csum[8];
    __shared__ int s_list[384];
    __shared__ int s_n;
    __shared__ float s_part[8][16];
    __shared__ float s_t[16];
    __shared__ float s_vals[384];

    for (int w = t; w < WPRP; w += 256) {
        unsigned b0 = g_bits[0][i * WPRP + w];
        unsigned b1 = g_bits[1][i * WPRP + w];
        unsigned b2 = g_bits[2][i * WPRP + w];
        s_b0[w] = b0; s_b1[w] = b1; s_b2[w] = b2;
        s_w[w] = b0 | b1 | b2;
    }
    __syncthreads();

    if (warp < 5) {
        int w = warp * 32 + lane;
        int c = __popc(s_w[w]);
        int x = c;
        #pragma unroll
        for (int off = 1; off < 32; off <<= 1) {
            int y = __shfl_up_sync(0xffffffffu, x, off);
            if (lane >= off) x += y;
        }
        s_base[w] = x - c;
        if (lane == 31) s_csum[warp] = x;
    }
    __syncthreads();
    if (t < 32) {
        int v = (lane < 5) ? s_csum[lane] : 0;
        int x = v;
        #pragma unroll
        for (int off = 1; off < 8; off <<= 1) {
            int y = __shfl_up_sync(0xffffffffu, x, off);
            if (lane >= off) x += y;
        }
        if (lane < 5) s_csum[lane] = x - v;
        if (lane == 4) s_n = x;
    }
    __syncthreads();
    for (int w = t; w < WPR; w += 256) {
        unsigned m = s_w[w];
        int base = s_base[w] + s_csum[w >> 5];
        int jb = w * 32;
        while (m) {
            int b = __ffs(m) - 1; m &= m - 1;
            s_list[base++] = jb + b;
        }
    }
    __syncthreads();
    int E = s_n;

    // ---- (a) union SpMM ----
    float4 acc = gather4<64>((const float4*)g_fs, s_list, E, sub, d4);
    #pragma unroll
    for (int off = 4; off < 32; off <<= 1) {
        acc.x += __shfl_xor_sync(0xffffffffu, acc.x, off);
        acc.y += __shfl_xor_sync(0xffffffffu, acc.y, off);
        acc.z += __shfl_xor_sync(0xffffffffu, acc.z, off);
        acc.w += __shfl_xor_sync(0xffffffffu, acc.w, off);
    }
    if (lane < 4) {
        s_part[warp][d4 * 4 + 0] = acc.x;
        s_part[warp][d4 * 4 + 1] = acc.y;
        s_part[warp][d4 * 4 + 2] = acc.z;
        s_part[warp][d4 * 4 + 3] = acc.w;
    }
    __syncthreads();
    if (t < 16) {
        float di = g_dinvu[i];
        float s = 0.f;
        #pragma unroll
        for (int wq = 0; wq < 8; wq++) s += s_part[wq][t];
        s_t[t] = di * (s + g_fs[i * DOUT + t]);
    }
    __syncthreads();
    if (t < NCLS) {
        float p = bf[t];
        #pragma unroll
        for (int o = 0; o < DOUT; o++)
            p = fmaf(s_t[o], Wf[o * NCLS + t], p);
        pred[i * NCLS + t] = p;
    }

    // ---- (b) per-nonzero attention values ----
    float4 A = *(const float4*)&g_atta[i * 4];
    for (int e = t; e < E; e += 256) {
        int j = s_list[e];
        float4 B = *(const float4*)&g_attb[j * 4];
        float s0 = __expf(fmaxf(A.x + B.x, 0.f));
        float s1 = __expf(fmaxf(A.y + B.y, 0.f));
        float s2 = __expf(fmaxf(A.z + B.z, 0.f));
        int w = j >> 5, b = j & 31;
        float num = (((s_b0[w] >> b) & 1u) ? s0 : 0.f) +
                    (((s_b1[w] >> b) & 1u) ? s1 : 0.f) +
                    (((s_b2[w] >> b) & 1u) ? s2 : 0.f);
        s_vals[e] = __fdividef(num, s0 + s1 + s2);
    }
    __syncthreads();

    // ---- (c) full A_meta row write (streaming) ----
    float4* arow = (float4*)(Am + (size_t)i * NN);
    for (int q = t; q < 1250; q += 256) {
        int w = q >> 3;
        unsigned mw = s_w[w];
        unsigned nib = (mw >> ((q & 7) * 4)) & 0xFu;
        float4 o = make_float4(0.f, 0.f, 0.f, 0.f);
        if (nib) {
            int base = s_base[w] + s_csum[w >> 5];
            int bsh = (q & 7) * 4;
            float v[4] = {0.f, 0.f, 0.f, 0.f};
            #pragma unroll
            for (int c = 0; c < 4; c++) {
                if ((nib >> c) & 1u) {
                    int b = bsh + c;
                    int idx = base + __popc(mw & ((1u << b) - 1u));
                    v[c] = s_vals[idx];
                }
            }
            o = make_float4(v[0], v[1], v[2], v[3]);
        }
        __stcs(arow + q, o);
    }
}

// ---------------------------------------------------------------------------
extern "C" void kernel_launch(void* const* d_in, const int* in_sizes, int n_in,
                              void* d_out, int out_size) {
    const float* features = (const float*)d_in[0];
    const float* adj      = (const float*)d_in[1];
    const float* W_gnn    = (const float*)d_in[2];
    const float* b_gnn    = (const float*)d_in[3];
    const float* att_w    = (const float*)d_in[4];
    const float* W_final  = (const float*)d_in[5];
    const float* b_final  = (const float*)d_in[6];

    float* out   = (float*)d_out;
    float* fmeta = out;                                        // [5000,16]
    float* Ameta = out + (size_t)NN * DOUT;                    // [5000,5000]
    float* pred  = out + (size_t)NN * DOUT + (size_t)NN * NN;  // [5000,100]

    k_prep<<<NN, 256>>>(adj, features, W_gnn);
    k_hatt<<<NN, 384>>>(b_gnn, att_w, fmeta);
    k_post<<<NN, 256>>>(W_final, b_final, pred, Ameta);
}